// round 1
// baseline (speedup 1.0000x reference)
#include <cuda_runtime.h>
#include <math.h>

#define BB 8
#define CC 256
#define MID 64
#define HH 128
#define WW 128
#define HWSZ (HH*WW)

// ---------------- scratch (static device arrays; no allocations) -------------
__device__ float d_xc[BB*HWSZ*MID];      // compress out, channels-last [b][p][64]
__device__ float d_h [BB*32*HWSZ];       // off1 out (gelu'd) [b][32][H][W]
__device__ float d_off[BB*18*HWSZ];      // offsets [b][18][H][W]
__device__ float d_xd[BB*HWSZ*MID];      // deform out, channels-last [b][p][64]
__device__ float d_xe[BB*CC*HWSZ];       // expand out [b][256][H][W]
__device__ float d_wt[9*MID*MID];        // deform weight transposed [k][c][o]
__device__ float d_part[BB*4*128*2];     // GN partial (sum,sumsq) per (b,g,tile)
__device__ float d_mv[BB*4*2];           // GN (mean, rstd) per (b,g)

__device__ __forceinline__ float gelu_exact(float v) {
    return 0.5f * v * (1.0f + erff(v * 0.70710678118654752440f));
}

// ---------------- deform weight transpose [o][c][k] -> [k][c][o] -------------
__global__ void transpose_w_kernel(const float* __restrict__ w) {
    int e = blockIdx.x * 256 + threadIdx.x;           // e < 9*64*64 = 36864
    int o = e / 576;
    int rem = e % 576;
    int c = rem / 9;
    int k = rem % 9;
    d_wt[(k*64 + c)*64 + o] = w[e];
}

// ---------------- compress: 1x1 conv 256->64, out channels-last --------------
__global__ void compress_kernel(const float* __restrict__ feat,
                                const float* __restrict__ w,
                                const float* __restrict__ bias) {
    __shared__ float w_s[128*64];                     // [c_local][m]
    int b = blockIdx.y;
    int p = blockIdx.x * 128 + threadIdx.x;
    float acc[64];
#pragma unroll
    for (int m = 0; m < 64; ++m) acc[m] = bias[m];

    for (int half = 0; half < 2; ++half) {
        __syncthreads();
        for (int e = threadIdx.x; e < 128*64; e += 128) {
            int cl = e >> 6, m = e & 63;
            w_s[e] = w[m*256 + half*128 + cl];
        }
        __syncthreads();
        const float* fp = feat + ((b*CC + half*128)*HWSZ) + p;
        for (int cl = 0; cl < 128; ++cl) {
            float fv = fp[cl*HWSZ];
            const float4* wr = (const float4*)(w_s + cl*64);
#pragma unroll
            for (int m4 = 0; m4 < 16; ++m4) {
                float4 wv = wr[m4];
                acc[4*m4+0] += fv*wv.x;
                acc[4*m4+1] += fv*wv.y;
                acc[4*m4+2] += fv*wv.z;
                acc[4*m4+3] += fv*wv.w;
            }
        }
    }
    float4* outp = (float4*)(d_xc + (b*HWSZ + p)*64);
#pragma unroll
    for (int m4 = 0; m4 < 16; ++m4)
        outp[m4] = make_float4(acc[4*m4], acc[4*m4+1], acc[4*m4+2], acc[4*m4+3]);
}

// ---------------- off1: 3x3 conv 2->32, pad 1, then exact GELU ---------------
__global__ void off1_kernel(const float* __restrict__ wind,
                            const float* __restrict__ w,
                            const float* __restrict__ bias) {
    int x = threadIdx.x;
    int y = blockIdx.x;
    int co = blockIdx.y;
    int b = blockIdx.z;
    float acc = bias[co];
    const float* wb = w + co*18;
#pragma unroll
    for (int ci = 0; ci < 2; ++ci) {
        const float* src = wind + (b*2 + ci)*HWSZ;
#pragma unroll
        for (int ky = 0; ky < 3; ++ky) {
            int yy = y + ky - 1;
            if (yy < 0 || yy >= HH) continue;
#pragma unroll
            for (int kx = 0; kx < 3; ++kx) {
                int xx = x + kx - 1;
                if (xx < 0 || xx >= WW) continue;
                acc += src[yy*WW + xx] * wb[ci*9 + ky*3 + kx];
            }
        }
    }
    d_h[(b*32 + co)*HWSZ + y*WW + x] = gelu_exact(acc);
}

// ---------------- off2: 3x3 conv 32->18, pad 1 -------------------------------
__global__ void off2_kernel(const float* __restrict__ w,
                            const float* __restrict__ bias) {
    __shared__ float tile[16*3*130];                  // [ci_local][ky][col]
    __shared__ float w_s[32*9*18];                    // [(ci*9+k)][co]
    int x = threadIdx.x;
    int y = blockIdx.x;
    int b = blockIdx.y;

    for (int e = threadIdx.x; e < 32*9*18; e += 128) {
        int co = e / 288;
        int rem = e % 288;                            // ci*9 + k
        w_s[rem*18 + co] = w[e];
    }

    float acc[18];
#pragma unroll
    for (int j = 0; j < 18; ++j) acc[j] = bias[j];

    for (int half = 0; half < 2; ++half) {
        __syncthreads();
        for (int e = threadIdx.x; e < 16*3*130; e += 128) {
            int cil = e / 390;
            int rem = e % 390;
            int ky = rem / 130;
            int col = rem % 130;
            int yy = y + ky - 1;
            int xx = col - 1;
            float v = 0.f;
            if (yy >= 0 && yy < HH && xx >= 0 && xx < WW)
                v = d_h[((b*32 + half*16 + cil)*HWSZ) + yy*WW + xx];
            tile[e] = v;
        }
        __syncthreads();
        for (int cil = 0; cil < 16; ++cil) {
#pragma unroll
            for (int ky = 0; ky < 3; ++ky) {
#pragma unroll
                for (int kx = 0; kx < 3; ++kx) {
                    float v = tile[(cil*3 + ky)*130 + x + kx];
                    const float* wp = w_s + ((half*16 + cil)*9 + ky*3 + kx)*18;
#pragma unroll
                    for (int j = 0; j < 18; ++j) acc[j] += v * wp[j];
                }
            }
        }
    }
#pragma unroll
    for (int j = 0; j < 18; ++j)
        d_off[(b*18 + j)*HWSZ + y*WW + x] = acc[j];
}

// ---------------- deform conv: bilinear sample + 64x64x9 gemm ----------------
// Block: 32 pixels (one x-strip), 128 threads = 16 o-groups x 8 pixel-groups.
__global__ void deform_kernel(const float* __restrict__ dbias) {
    __shared__ float w_s[64*64];                      // [c][o] for current tap k
    __shared__ float s_k[64*33];                      // sampled [c][pix] (pad 33)
    int b = blockIdx.y;
    int tile = blockIdx.x;
    int p0 = tile * 32;
    int y  = p0 >> 7;
    int xb = p0 & 127;
    int t = threadIdx.x;
    int og = t & 15;                                  // outputs 4*og..4*og+3
    int pg = t >> 4;                                  // pixels  4*pg..4*pg+3

    float acc[4][4];
#pragma unroll
    for (int i = 0; i < 4; ++i)
#pragma unroll
        for (int j = 0; j < 4; ++j) acc[i][j] = 0.f;

    const float* offb = d_off + b*18*HWSZ;
    const float* xcb  = d_xc + b*HWSZ*64;

    for (int k = 0; k < 9; ++k) {
        __syncthreads();                              // prev gemm done
        // stage weights for tap k
        {
            const float4* src = (const float4*)(d_wt + k*4096);
            float4* dst = (float4*)w_s;
#pragma unroll
            for (int r = 0; r < 8; ++r) dst[r*128 + t] = src[r*128 + t];
        }
        // bilinear sampling: 64 channels x 32 pixels
        int ky = k/3 - 1, kx = k%3 - 1;
#pragma unroll 2
        for (int it = 0; it < 16; ++it) {
            int idx = it*128 + t;
            int pix = idx >> 6;
            int c   = idx & 63;
            int x = xb + pix;
            float dy = offb[(2*k  )*HWSZ + y*WW + x];
            float dx = offb[(2*k+1)*HWSZ + y*WW + x];
            float py = (float)(y + ky) + dy;
            float px = (float)(x + kx) + dx;
            float fy = floorf(py), fx = floorf(px);
            float wy = py - fy,  wx = px - fx;
            int iy = (int)fy, ix = (int)fx;
            bool y0ok = (iy >= 0)   && (iy < HH);
            bool y1ok = (iy+1 >= 0) && (iy+1 < HH);
            bool x0ok = (ix >= 0)   && (ix < WW);
            bool x1ok = (ix+1 >= 0) && (ix+1 < WW);
            float v00 = (y0ok && x0ok) ? xcb[(iy*WW + ix    )*64 + c] : 0.f;
            float v01 = (y0ok && x1ok) ? xcb[(iy*WW + ix + 1)*64 + c] : 0.f;
            float v10 = (y1ok && x0ok) ? xcb[((iy+1)*WW + ix    )*64 + c] : 0.f;
            float v11 = (y1ok && x1ok) ? xcb[((iy+1)*WW + ix + 1)*64 + c] : 0.f;
            s_k[c*33 + pix] = v00*(1.f-wy)*(1.f-wx) + v01*(1.f-wy)*wx
                            + v10*wy*(1.f-wx)       + v11*wy*wx;
        }
        __syncthreads();
        // gemm: acc[o][pix] += w[c][o] * s[c][pix]
#pragma unroll 4
        for (int c = 0; c < 64; ++c) {
            float4 w4 = *(const float4*)(w_s + c*64 + 4*og);
            const float* sp = s_k + c*33 + 4*pg;
            float s0 = sp[0], s1 = sp[1], s2 = sp[2], s3 = sp[3];
            acc[0][0] += w4.x*s0; acc[0][1] += w4.x*s1; acc[0][2] += w4.x*s2; acc[0][3] += w4.x*s3;
            acc[1][0] += w4.y*s0; acc[1][1] += w4.y*s1; acc[1][2] += w4.y*s2; acc[1][3] += w4.y*s3;
            acc[2][0] += w4.z*s0; acc[2][1] += w4.z*s1; acc[2][2] += w4.z*s2; acc[2][3] += w4.z*s3;
            acc[3][0] += w4.w*s0; acc[3][1] += w4.w*s1; acc[3][2] += w4.w*s2; acc[3][3] += w4.w*s3;
        }
    }
    float b0 = dbias[4*og+0], b1 = dbias[4*og+1], b2 = dbias[4*og+2], b3 = dbias[4*og+3];
#pragma unroll
    for (int j = 0; j < 4; ++j) {
        int p = p0 + 4*pg + j;
        float4 v = make_float4(acc[0][j]+b0, acc[1][j]+b1, acc[2][j]+b2, acc[3][j]+b3);
        *(float4*)(d_xd + (b*HWSZ + p)*64 + 4*og) = v;
    }
}

// ---------------- expand 1x1 conv 64->256 (per 64-ch group) + GN partials ----
__global__ void expand_kernel(const float* __restrict__ w,
                              const float* __restrict__ bias) {
    __shared__ float w_s[64*64];                      // [m][j] (j = co within group)
    __shared__ float red[256];
    int tile = blockIdx.x, g = blockIdx.y, b = blockIdx.z;
    int t = threadIdx.x;
    int p = tile*128 + t;

    for (int e = t; e < 4096; e += 128) {
        int m = e >> 6, j = e & 63;
        w_s[e] = w[(g*64 + j)*64 + m];
    }
    __syncthreads();

    float acc[64];
#pragma unroll
    for (int j = 0; j < 64; ++j) acc[j] = 0.f;

    const float4* xv4 = (const float4*)(d_xd + (b*HWSZ + p)*64);
    for (int m4 = 0; m4 < 16; ++m4) {
        float4 xv = xv4[m4];
        float xa[4] = {xv.x, xv.y, xv.z, xv.w};
#pragma unroll
        for (int mm = 0; mm < 4; ++mm) {
            float v = xa[mm];
            const float4* wr = (const float4*)(w_s + (4*m4 + mm)*64);
#pragma unroll
            for (int j4 = 0; j4 < 16; ++j4) {
                float4 wv = wr[j4];
                acc[4*j4+0] += v*wv.x;
                acc[4*j4+1] += v*wv.y;
                acc[4*j4+2] += v*wv.z;
                acc[4*j4+3] += v*wv.w;
            }
        }
    }

    float lsum = 0.f, lssq = 0.f;
    int co0 = g*64;
#pragma unroll
    for (int j = 0; j < 64; ++j) {
        float val = acc[j] + bias[co0 + j];
        d_xe[((b*CC + co0 + j)*HWSZ) + p] = val;
        lsum += val;
        lssq += val*val;
    }
    red[t] = lsum; red[128 + t] = lssq;
    __syncthreads();
    for (int s2 = 64; s2 > 0; s2 >>= 1) {
        if (t < s2) { red[t] += red[t+s2]; red[128+t] += red[128+t+s2]; }
        __syncthreads();
    }
    if (t == 0) {
        int bg = b*4 + g;
        d_part[(bg*128 + tile)*2 + 0] = red[0];
        d_part[(bg*128 + tile)*2 + 1] = red[128];
    }
}

// ---------------- GN stats finalize ------------------------------------------
__global__ void gn_finalize_kernel() {
    __shared__ float red[256];
    int bg = blockIdx.x;
    int t = threadIdx.x;                              // 128
    red[t]       = d_part[(bg*128 + t)*2 + 0];
    red[128 + t] = d_part[(bg*128 + t)*2 + 1];
    __syncthreads();
    for (int s2 = 64; s2 > 0; s2 >>= 1) {
        if (t < s2) { red[t] += red[t+s2]; red[128+t] += red[128+t+s2]; }
        __syncthreads();
    }
    if (t == 0) {
        const float N = 64.0f * (float)HWSZ;
        float mean = red[0] / N;
        float var = red[128] / N - mean*mean;
        var = fmaxf(var, 0.f);
        d_mv[bg*2 + 0] = mean;
        d_mv[bg*2 + 1] = rsqrtf(var + 1e-5f);
    }
}

// ---------------- final: residual + gelu(groupnorm) --------------------------
__global__ void final_kernel(const float* __restrict__ feat,
                             const float* __restrict__ gamma,
                             const float* __restrict__ beta,
                             float* __restrict__ out) {
    int idx = blockIdx.x * 256 + threadIdx.x;
    int e = idx * 4;
    int c = (e >> 14) & 255;
    int b = e >> 22;
    int bg = b*4 + (c >> 6);
    float mean = d_mv[bg*2], rstd = d_mv[bg*2 + 1];
    float gaf = gamma[c];
    float ga = gaf * rstd;
    float be = beta[c] - mean * rstd * gaf;           // y = xe*ga + be
    float4 xe = *(const float4*)(d_xe + e);
    float4 f  = *(const float4*)(feat + e);
    float4 o;
    o.x = f.x + gelu_exact(xe.x*ga + be);
    o.y = f.y + gelu_exact(xe.y*ga + be);
    o.z = f.z + gelu_exact(xe.z*ga + be);
    o.w = f.w + gelu_exact(xe.w*ga + be);
    *(float4*)(out + e) = o;
}

// ---------------- launch ------------------------------------------------------
extern "C" void kernel_launch(void* const* d_in, const int* in_sizes, int n_in,
                              void* d_out, int out_size) {
    const float* features   = (const float*)d_in[0];
    const float* wind_uv    = (const float*)d_in[1];
    const float* compress_w = (const float*)d_in[2];
    const float* compress_b = (const float*)d_in[3];
    const float* off1_w     = (const float*)d_in[4];
    const float* off1_b     = (const float*)d_in[5];
    const float* off2_w     = (const float*)d_in[6];
    const float* off2_b     = (const float*)d_in[7];
    const float* deform_w   = (const float*)d_in[8];
    const float* deform_b   = (const float*)d_in[9];
    const float* expand_w   = (const float*)d_in[10];
    const float* expand_b   = (const float*)d_in[11];
    const float* gn_gamma   = (const float*)d_in[12];
    const float* gn_beta    = (const float*)d_in[13];
    float* out = (float*)d_out;

    transpose_w_kernel<<<144, 256>>>(deform_w);
    compress_kernel<<<dim3(128, 8), 128>>>(features, compress_w, compress_b);
    off1_kernel<<<dim3(128, 32, 8), 128>>>(wind_uv, off1_w, off1_b);
    off2_kernel<<<dim3(128, 8), 128>>>(off2_w, off2_b);
    deform_kernel<<<dim3(512, 8), 128>>>(deform_b);
    expand_kernel<<<dim3(128, 4, 8), 128>>>(expand_w, expand_b);
    gn_finalize_kernel<<<32, 128>>>();
    final_kernel<<<32768, 256>>>(features, gn_gamma, gn_beta, out);
}

// round 2
// speedup vs baseline: 1.8795x; 1.8795x over previous
#include <cuda_runtime.h>
#include <math.h>

#define BB 8
#define CC 256
#define MID 64
#define HH 128
#define WW 128
#define HW 16384

// ---------------- scratch (static device arrays; no allocations) -------------
__device__ float d_xc[BB*HW*MID];       // compress out, channels-last [b][p][64]
__device__ float d_h [BB*32*HW];        // off1 out (gelu'd) [b][32][H][W]
__device__ float d_off[BB*18*HW];       // offsets [b][18][H][W]
__device__ float d_xd[BB*HW*MID];       // deform out, channels-last [b][p][64]
__device__ float d_xe[BB*CC*HW];        // expand out [b][256][H][W]
__device__ float d_wt[9*MID*MID];       // deform weight [k][o][c]
__device__ float d_part[BB*4*128*2];    // GN partial (sum,sumsq) per (b,g,tile)
__device__ float d_mv[BB*4*2];          // GN (mean, rstd) per (b,g)

__device__ __forceinline__ float gelu_exact(float v) {
    return 0.5f * v * (1.0f + erff(v * 0.70710678118654752440f));
}

__device__ __forceinline__ unsigned f2tf(float f) {
    unsigned u; asm("cvt.rna.tf32.f32 %0, %1;" : "=r"(u) : "f"(f)); return u;
}

__device__ __forceinline__ void mma8(float4& d, const unsigned* a, unsigned b0, unsigned b1) {
    asm volatile(
        "mma.sync.aligned.m16n8k8.row.col.f32.tf32.tf32.f32 "
        "{%0,%1,%2,%3}, {%4,%5,%6,%7}, {%8,%9}, {%0,%1,%2,%3};\n"
        : "+f"(d.x), "+f"(d.y), "+f"(d.z), "+f"(d.w)
        : "r"(a[0]), "r"(a[1]), "r"(a[2]), "r"(a[3]), "r"(b0), "r"(b1));
}

// ---------------- deform weight transpose [o][c][k] -> [k][o][c] -------------
__global__ void transpose_w_kernel(const float* __restrict__ w) {
    int e = blockIdx.x * 256 + threadIdx.x;           // e < 9*64*64 = 36864
    int k = e >> 12;
    int rem = e & 4095;
    int o = rem >> 6;
    int c = rem & 63;
    d_wt[e] = w[(o*64 + c)*9 + k];
}

// ---------------- compress: 1x1 conv 256->64 via tf32 mma --------------------
// Block: 128 pixels x 64 out channels, K=256 staged in BK=32 chunks.
__global__ void compress_mma(const float* __restrict__ feat,
                             const float* __restrict__ w,
                             const float* __restrict__ bias) {
    __shared__ unsigned As[32*132];                   // [k][m] tf32, pad 132
    __shared__ unsigned Bs[64*36];                    // [n][k] tf32, pad 36
    int b = blockIdx.y;
    int p0 = blockIdx.x * 128;
    int t = threadIdx.x;
    int warp = t >> 5, lane = t & 31;
    int g = lane >> 2, tg = lane & 3;
    int wm = warp & 3, wn = warp >> 2;

    float4 acc[2][4];
#pragma unroll
    for (int i = 0; i < 2; ++i)
#pragma unroll
        for (int j = 0; j < 4; ++j) acc[i][j] = make_float4(0.f,0.f,0.f,0.f);

    const float* fb = feat + (size_t)b*CC*HW + p0;
    for (int kb = 0; kb < 8; ++kb) {
        __syncthreads();
        // A: 32 k-rows x 128 pixels
#pragma unroll
        for (int i = 0; i < 4; ++i) {
            int idx = t + i*256;                      // < 1024 float4
            int r = idx >> 5, m4 = idx & 31;
            float4 v = *(const float4*)(fb + (size_t)(kb*32 + r)*HW + m4*4);
            unsigned* dst = As + r*132 + m4*4;
            dst[0]=f2tf(v.x); dst[1]=f2tf(v.y); dst[2]=f2tf(v.z); dst[3]=f2tf(v.w);
        }
        // B: 64 n-rows x 32 k
#pragma unroll
        for (int i = 0; i < 2; ++i) {
            int idx = t + i*256;                      // < 512 float4
            int n = idx >> 3, k4 = idx & 7;
            float4 v = *(const float4*)(w + n*256 + kb*32 + k4*4);
            unsigned* dst = Bs + n*36 + k4*4;
            dst[0]=f2tf(v.x); dst[1]=f2tf(v.y); dst[2]=f2tf(v.z); dst[3]=f2tf(v.w);
        }
        __syncthreads();
#pragma unroll
        for (int ks = 0; ks < 4; ++ks) {
            int kk = ks*8;
            unsigned a[2][4];
#pragma unroll
            for (int i = 0; i < 2; ++i) {
                int row = wm*32 + i*16 + g;
                a[i][0] = As[(kk+tg  )*132 + row];
                a[i][1] = As[(kk+tg  )*132 + row + 8];
                a[i][2] = As[(kk+tg+4)*132 + row];
                a[i][3] = As[(kk+tg+4)*132 + row + 8];
            }
#pragma unroll
            for (int j = 0; j < 4; ++j) {
                int col = wn*32 + j*8 + g;
                unsigned b0 = Bs[col*36 + kk + tg];
                unsigned b1 = Bs[col*36 + kk + tg + 4];
                mma8(acc[0][j], a[0], b0, b1);
                mma8(acc[1][j], a[1], b0, b1);
            }
        }
    }
    float* outb = d_xc + ((size_t)b*HW + p0)*64;
#pragma unroll
    for (int i = 0; i < 2; ++i) {
        int row = wm*32 + i*16 + g;
#pragma unroll
        for (int j = 0; j < 4; ++j) {
            int col = wn*32 + j*8 + 2*tg;
            float bx = bias[col], by = bias[col+1];
            *(float2*)(outb + row*64 + col)     = make_float2(acc[i][j].x + bx, acc[i][j].y + by);
            *(float2*)(outb + (row+8)*64 + col) = make_float2(acc[i][j].z + bx, acc[i][j].w + by);
        }
    }
}

// ---------------- off1: 3x3 conv 2->32, pad 1, exact GELU --------------------
__global__ void off1_v2(const float* __restrict__ wind,
                        const float* __restrict__ w,
                        const float* __restrict__ bias) {
    __shared__ float tile[2*3*130];
    __shared__ float wsm[18*32];
    int b = blockIdx.y, y = blockIdx.x;
    int t = threadIdx.x;                              // 128
    for (int e = t; e < 576; e += 128) {
        int co = e / 18, rem = e % 18;
        wsm[rem*32 + co] = w[e];
    }
    for (int e = t; e < 780; e += 128) {
        int ci = e / 390, rem = e % 390;
        int ry = rem / 130, col = rem % 130;
        int yy = y - 1 + ry, xx = col - 1;
        float v = 0.f;
        if (yy >= 0 && yy < HH && xx >= 0 && xx < WW)
            v = wind[(b*2 + ci)*HW + yy*WW + xx];
        tile[e] = v;
    }
    __syncthreads();
    float acc[32];
#pragma unroll
    for (int j = 0; j < 32; ++j) acc[j] = bias[j];
#pragma unroll
    for (int ci = 0; ci < 2; ++ci)
#pragma unroll
        for (int ky = 0; ky < 3; ++ky)
#pragma unroll
            for (int kx = 0; kx < 3; ++kx) {
                float v = tile[ci*390 + ky*130 + t + kx];
                const float* wp = wsm + (ci*9 + ky*3 + kx)*32;
#pragma unroll
                for (int j = 0; j < 32; ++j) acc[j] += v * wp[j];
            }
#pragma unroll
    for (int j = 0; j < 32; ++j)
        d_h[(b*32 + j)*HW + y*WW + t] = gelu_exact(acc[j]);
}

// ---------------- off2: 3x3 conv 32->18, pad 1 -------------------------------
// Block: 256 threads = 2 rows x 128 cols; ci staged in chunks of 8.
__global__ void off2_v2(const float* __restrict__ w,
                        const float* __restrict__ bias) {
    __shared__ float wsm[288*18];                     // [(ci*9+kk)][co]
    __shared__ float tile[8*4*130];                   // [cil][ry][col]
    int b = blockIdx.y;
    int y0 = blockIdx.x * 2;
    int t = threadIdx.x;                              // 256
    int yl = t >> 7, x = t & 127;

    for (int e = t; e < 5184; e += 256) {
        int co = e / 288, rem = e % 288;
        wsm[rem*18 + co] = w[e];
    }
    float acc[18];
#pragma unroll
    for (int j = 0; j < 18; ++j) acc[j] = bias[j];

    for (int ch = 0; ch < 4; ++ch) {
        __syncthreads();
        for (int e = t; e < 4160; e += 256) {
            int cil = e / 520, rem = e % 520;
            int ry = rem / 130, col = rem % 130;
            int yy = y0 - 1 + ry, xx = col - 1;
            float v = 0.f;
            if (yy >= 0 && yy < HH && xx >= 0 && xx < WW)
                v = d_h[((b*32 + ch*8 + cil)*HW) + yy*WW + xx];
            tile[e] = v;
        }
        __syncthreads();
        for (int cil = 0; cil < 8; ++cil) {
#pragma unroll
            for (int ky = 0; ky < 3; ++ky) {
                const float* base = tile + cil*520 + (yl + ky)*130 + x;
                float v0 = base[0], v1 = base[1], v2 = base[2];
                const float* w0 = wsm + ((ch*8 + cil)*9 + ky*3)*18;
#pragma unroll
                for (int j = 0; j < 18; ++j)
                    acc[j] += v0*w0[j] + v1*w0[18 + j] + v2*w0[36 + j];
            }
        }
    }
    int y = y0 + yl;
#pragma unroll
    for (int j = 0; j < 18; ++j)
        d_off[(b*18 + j)*HW + y*WW + x] = acc[j];
}

// ---------------- deform conv: bilinear sample + tf32 mma --------------------
// Block: 128 pixels (one row), loop over 9 taps.
__global__ void deform_mma(const float* __restrict__ dbias) {
    __shared__ unsigned Ss[128*68];                   // sampled [pix][c] tf32
    __shared__ unsigned Ws[64*68];                    // weights [o][c] tf32
    int b = blockIdx.y;
    int y = blockIdx.x;
    int t = threadIdx.x;                              // 256
    int warp = t >> 5, lane = t & 31;
    int g = lane >> 2, tg = lane & 3;
    int wm = warp & 3, wn = warp >> 2;

    float4 acc[2][4];
#pragma unroll
    for (int i = 0; i < 2; ++i)
#pragma unroll
        for (int j = 0; j < 4; ++j) acc[i][j] = make_float4(0.f,0.f,0.f,0.f);

    const float* offb = d_off + (size_t)b*18*HW + y*WW;
    const float* xcb  = d_xc + (size_t)b*HW*64;
    int pix = t >> 1, half = t & 1;

    for (int k = 0; k < 9; ++k) {
        if (k) __syncthreads();
        // weights for tap k: [o][c]
#pragma unroll
        for (int i = 0; i < 4; ++i) {
            int idx = t + i*256;                      // < 1024 float4
            int n = idx >> 4, k4 = idx & 15;
            float4 v = *(const float4*)(d_wt + k*4096 + n*64 + k4*4);
            unsigned* dst = Ws + n*68 + k4*4;
            dst[0]=f2tf(v.x); dst[1]=f2tf(v.y); dst[2]=f2tf(v.z); dst[3]=f2tf(v.w);
        }
        // bilinear sampling: 2 threads/pixel, 32 channels each
        {
            int x = pix;
            float dy = offb[(2*k  )*HW + x];
            float dx = offb[(2*k+1)*HW + x];
            float py = (float)(y + k/3 - 1) + dy;
            float px = (float)(x + k%3 - 1) + dx;
            float fy = floorf(py), fx = floorf(px);
            float wy = py - fy, wx = px - fx;
            int iy = (int)fy, ix = (int)fx;
            bool y0ok = (iy >= 0)  && (iy < HH);
            bool y1ok = (iy >= -1) && (iy < HH-1);
            bool x0ok = (ix >= 0)  && (ix < WW);
            bool x1ok = (ix >= -1) && (ix < WW-1);
            float w00 = (1.f-wy)*(1.f-wx), w01 = (1.f-wy)*wx;
            float w10 = wy*(1.f-wx),       w11 = wy*wx;
            const float* r00 = xcb + ((size_t)iy*WW + ix)*64 + half*32;
            const float* r01 = r00 + 64;
            const float* r10 = r00 + WW*64;
            const float* r11 = r10 + 64;
            unsigned* dst = Ss + pix*68 + half*32;
            float4 zf = make_float4(0.f,0.f,0.f,0.f);
#pragma unroll
            for (int c4 = 0; c4 < 8; ++c4) {
                float4 v00 = (y0ok && x0ok) ? *(const float4*)(r00 + c4*4) : zf;
                float4 v01 = (y0ok && x1ok) ? *(const float4*)(r01 + c4*4) : zf;
                float4 v10 = (y1ok && x0ok) ? *(const float4*)(r10 + c4*4) : zf;
                float4 v11 = (y1ok && x1ok) ? *(const float4*)(r11 + c4*4) : zf;
                dst[c4*4+0] = f2tf(w00*v00.x + w01*v01.x + w10*v10.x + w11*v11.x);
                dst[c4*4+1] = f2tf(w00*v00.y + w01*v01.y + w10*v10.y + w11*v11.y);
                dst[c4*4+2] = f2tf(w00*v00.z + w01*v01.z + w10*v10.z + w11*v11.z);
                dst[c4*4+3] = f2tf(w00*v00.w + w01*v01.w + w10*v10.w + w11*v11.w);
            }
        }
        __syncthreads();
#pragma unroll
        for (int ks = 0; ks < 8; ++ks) {
            int kk = ks*8;
            unsigned a[2][4];
#pragma unroll
            for (int i = 0; i < 2; ++i) {
                int row = wm*32 + i*16 + g;
                a[i][0] = Ss[row*68 + kk + tg];
                a[i][1] = Ss[(row+8)*68 + kk + tg];
                a[i][2] = Ss[row*68 + kk + tg + 4];
                a[i][3] = Ss[(row+8)*68 + kk + tg + 4];
            }
#pragma unroll
            for (int j = 0; j < 4; ++j) {
                int col = wn*32 + j*8 + g;
                unsigned b0 = Ws[col*68 + kk + tg];
                unsigned b1 = Ws[col*68 + kk + tg + 4];
                mma8(acc[0][j], a[0], b0, b1);
                mma8(acc[1][j], a[1], b0, b1);
            }
        }
    }
    float* outb = d_xd + ((size_t)b*HW + y*WW)*64;
#pragma unroll
    for (int i = 0; i < 2; ++i) {
        int row = wm*32 + i*16 + g;
#pragma unroll
        for (int j = 0; j < 4; ++j) {
            int col = wn*32 + j*8 + 2*tg;
            float bx = dbias[col], by = dbias[col+1];
            *(float2*)(outb + row*64 + col)     = make_float2(acc[i][j].x + bx, acc[i][j].y + by);
            *(float2*)(outb + (row+8)*64 + col) = make_float2(acc[i][j].z + bx, acc[i][j].w + by);
        }
    }
}

// ---------------- expand 1x1 conv 64->256 via tf32 mma + GN partials ---------
__global__ void expand_mma(const float* __restrict__ w,
                           const float* __restrict__ bias) {
    __shared__ unsigned Xs[128*68];                   // [pix][m] tf32 (reused as out stage)
    __shared__ unsigned Ws[64*68];                    // [n][m] tf32 (reused for reduce)
    int tileI = blockIdx.x, gI = blockIdx.y, b = blockIdx.z;
    int p0 = tileI * 128;
    int t = threadIdx.x;                              // 256
    int warp = t >> 5, lane = t & 31;
    int g = lane >> 2, tg = lane & 3;
    int wm = warp & 3, wn = warp >> 2;

    // load X tile
#pragma unroll
    for (int i = 0; i < 8; ++i) {
        int idx = t + i*256;                          // < 2048 float4
        int row = idx >> 4, c4 = idx & 15;
        float4 v = *(const float4*)(d_xd + ((size_t)b*HW + p0 + row)*64 + c4*4);
        unsigned* dst = Xs + row*68 + c4*4;
        dst[0]=f2tf(v.x); dst[1]=f2tf(v.y); dst[2]=f2tf(v.z); dst[3]=f2tf(v.w);
    }
    // load W tile for group gI
#pragma unroll
    for (int i = 0; i < 4; ++i) {
        int idx = t + i*256;                          // < 1024 float4
        int n = idx >> 4, k4 = idx & 15;
        float4 v = *(const float4*)(w + (gI*64 + n)*64 + k4*4);
        unsigned* dst = Ws + n*68 + k4*4;
        dst[0]=f2tf(v.x); dst[1]=f2tf(v.y); dst[2]=f2tf(v.z); dst[3]=f2tf(v.w);
    }
    __syncthreads();

    float4 acc[2][4];
#pragma unroll
    for (int i = 0; i < 2; ++i)
#pragma unroll
        for (int j = 0; j < 4; ++j) acc[i][j] = make_float4(0.f,0.f,0.f,0.f);

#pragma unroll
    for (int ks = 0; ks < 8; ++ks) {
        int kk = ks*8;
        unsigned a[2][4];
#pragma unroll
        for (int i = 0; i < 2; ++i) {
            int row = wm*32 + i*16 + g;
            a[i][0] = Xs[row*68 + kk + tg];
            a[i][1] = Xs[(row+8)*68 + kk + tg];
            a[i][2] = Xs[row*68 + kk + tg + 4];
            a[i][3] = Xs[(row+8)*68 + kk + tg + 4];
        }
#pragma unroll
        for (int j = 0; j < 4; ++j) {
            int col = wn*32 + j*8 + g;
            unsigned b0 = Ws[col*68 + kk + tg];
            unsigned b1 = Ws[col*68 + kk + tg + 4];
            mma8(acc[0][j], a[0], b0, b1);
            mma8(acc[1][j], a[1], b0, b1);
        }
    }
    __syncthreads();                                  // done reading Xs/Ws

    // stage outputs (pad-65 layout for conflict-free column reads) + GN sums
    float* OutS = (float*)Xs;                         // 128*65 <= 128*68
    float lsum = 0.f, lssq = 0.f;
#pragma unroll
    for (int i = 0; i < 2; ++i) {
        int row = wm*32 + i*16 + g;
#pragma unroll
        for (int j = 0; j < 4; ++j) {
            int col = wn*32 + j*8 + 2*tg;
            float bx = bias[gI*64 + col], by = bias[gI*64 + col + 1];
            float v0 = acc[i][j].x + bx, v1 = acc[i][j].y + by;
            float v2 = acc[i][j].z + bx, v3 = acc[i][j].w + by;
            OutS[row*65 + col]       = v0;
            OutS[row*65 + col + 1]   = v1;
            OutS[(row+8)*65 + col]   = v2;
            OutS[(row+8)*65 + col+1] = v3;
            lsum += v0 + v1 + v2 + v3;
            lssq += v0*v0 + v1*v1 + v2*v2 + v3*v3;
        }
    }
    float* redp = (float*)Ws;
    redp[t] = lsum; redp[256 + t] = lssq;
    __syncthreads();
    for (int s = 128; s > 0; s >>= 1) {
        if (t < s) { redp[t] += redp[t+s]; redp[256+t] += redp[256+t+s]; }
        __syncthreads();
    }
    if (t == 0) {
        int bg = b*4 + gI;
        d_part[(bg*128 + tileI)*2 + 0] = redp[0];
        d_part[(bg*128 + tileI)*2 + 1] = redp[256];
    }
    // coalesced NCHW store
    float* xeb = d_xe + ((size_t)b*CC + gI*64)*HW + p0;
#pragma unroll
    for (int i = 0; i < 32; ++i) {
        int e = t + i*256;                            // < 8192
        int co = e >> 7, px = e & 127;
        xeb[(size_t)co*HW + px] = OutS[px*65 + co];
    }
}

// ---------------- GN stats finalize ------------------------------------------
__global__ void gn_finalize_kernel() {
    __shared__ float red[256];
    int bg = blockIdx.x;
    int t = threadIdx.x;                              // 128
    red[t]       = d_part[(bg*128 + t)*2 + 0];
    red[128 + t] = d_part[(bg*128 + t)*2 + 1];
    __syncthreads();
    for (int s = 64; s > 0; s >>= 1) {
        if (t < s) { red[t] += red[t+s]; red[128+t] += red[128+t+s]; }
        __syncthreads();
    }
    if (t == 0) {
        const float N = 64.0f * (float)HW;
        float mean = red[0] / N;
        float var = red[128] / N - mean*mean;
        var = fmaxf(var, 0.f);
        d_mv[bg*2 + 0] = mean;
        d_mv[bg*2 + 1] = rsqrtf(var + 1e-5f);
    }
}

// ---------------- final: residual + gelu(groupnorm) --------------------------
__global__ void final_kernel(const float* __restrict__ feat,
                             const float* __restrict__ gamma,
                             const float* __restrict__ beta,
                             float* __restrict__ out) {
    int idx = blockIdx.x * 256 + threadIdx.x;
    int e = idx * 4;
    int c = (e >> 14) & 255;
    int b = e >> 22;
    int bg = b*4 + (c >> 6);
    float mean = d_mv[bg*2], rstd = d_mv[bg*2 + 1];
    float gaf = gamma[c];
    float ga = gaf * rstd;
    float be = beta[c] - mean * rstd * gaf;
    float4 xe = *(const float4*)(d_xe + e);
    float4 f  = *(const float4*)(feat + e);
    float4 o;
    o.x = f.x + gelu_exact(xe.x*ga + be);
    o.y = f.y + gelu_exact(xe.y*ga + be);
    o.z = f.z + gelu_exact(xe.z*ga + be);
    o.w = f.w + gelu_exact(xe.w*ga + be);
    *(float4*)(out + e) = o;
}

// ---------------- launch ------------------------------------------------------
extern "C" void kernel_launch(void* const* d_in, const int* in_sizes, int n_in,
                              void* d_out, int out_size) {
    const float* features   = (const float*)d_in[0];
    const float* wind_uv    = (const float*)d_in[1];
    const float* compress_w = (const float*)d_in[2];
    const float* compress_b = (const float*)d_in[3];
    const float* off1_w     = (const float*)d_in[4];
    const float* off1_b     = (const float*)d_in[5];
    const float* off2_w     = (const float*)d_in[6];
    const float* off2_b     = (const float*)d_in[7];
    const float* deform_w   = (const float*)d_in[8];
    const float* deform_b   = (const float*)d_in[9];
    const float* expand_w   = (const float*)d_in[10];
    const float* expand_b   = (const float*)d_in[11];
    const float* gn_gamma   = (const float*)d_in[12];
    const float* gn_beta    = (const float*)d_in[13];
    float* out = (float*)d_out;

    transpose_w_kernel<<<144, 256>>>(deform_w);
    compress_mma<<<dim3(128, 8), 256>>>(features, compress_w, compress_b);
    off1_v2<<<dim3(128, 8), 128>>>(wind_uv, off1_w, off1_b);
    off2_v2<<<dim3(64, 8), 256>>>(off2_w, off2_b);
    deform_mma<<<dim3(128, 8), 256>>>(deform_b);
    expand_mma<<<dim3(128, 4, 8), 256>>>(expand_w, expand_b);
    gn_finalize_kernel<<<32, 128>>>();
    final_kernel<<<32768, 256>>>(features, gn_gamma, gn_beta, out);
}